// round 12
// baseline (speedup 1.0000x reference)
#include <cuda_runtime.h>
#include <cuda_fp16.h>
#include <stdint.h>

// NeuralODE RK4, fp16 mma (m16n8k16, fp32 accum), sm_103a.
// R12 = R5 (best 833us) + depth-2 software pipeline (B and A prefetched 2 kt
// ahead at unchanged register pressure) + biases in SMEM (frees 16 regs of
// nominal pressure) + f32 tanh.approx. 64 CTAs x 256 threads, W1 in SMEM,
// W2 persistent in registers.

#define ZDIM 256
#define TLEN 128
#define MROW 16
#define NCTA 64
#define NKT  16           // K/16
#define NNT  32           // N/8
#define ASP  132          // A smem row stride in half2 words (conflict-free)
#define WREC (NKT * NNT * 32)          // uint2 records per matrix (128KB)

#define SMEM_W1   0
#define SMEM_ATF  (WREC * 8)                       // 131072
#define SMEM_HTF  (SMEM_ATF + MROW * ASP * 4)
#define SMEM_B1   (SMEM_HTF + MROW * ASP * 4)
#define SMEM_B2   (SMEM_B1 + ZDIM * 4)
#define SMEM_TOT  (SMEM_B2 + ZDIM * 4)             // ~146.5 KB

__device__ uint2 WfG[2 * WREC];   // fragment-layout fp16 weights (prep output)

// ---- prep: W[k][n] row-major fp32 -> fp16 B-fragment layout ----
__global__ void prep_kernel(const float* __restrict__ W1, const float* __restrict__ W2)
{
    int idx = blockIdx.x * blockDim.x + threadIdx.x;
    if (idx >= 2 * WREC) return;
    int lane = idx & 31;
    int nt   = (idx >> 5) & 31;
    int kt   = (idx >> 10) & 15;
    int g    = idx >> 14;
    const float* W = g ? W2 : W1;
    int k0 = kt * 16 + 2 * (lane & 3);
    int n  = nt * 8 + (lane >> 2);
    __half2 lo = __floats2half2_rn(W[k0 * ZDIM + n],       W[(k0 + 1) * ZDIM + n]);
    __half2 hi = __floats2half2_rn(W[(k0 + 8) * ZDIM + n], W[(k0 + 9) * ZDIM + n]);
    uint2 v;
    v.x = *reinterpret_cast<unsigned*>(&lo);
    v.y = *reinterpret_cast<unsigned*>(&hi);
    WfG[idx] = v;
}

#define MMA16(ACC, A0, A1, A2, A3, B) \
    asm volatile("mma.sync.aligned.m16n8k16.row.col.f32.f16.f16.f32 " \
                 "{%0,%1,%2,%3}, {%4,%5,%6,%7}, {%8,%9}, {%0,%1,%2,%3};" \
                 : "+f"(ACC[0]), "+f"(ACC[1]), "+f"(ACC[2]), "+f"(ACC[3]) \
                 : "r"(A0), "r"(A1), "r"(A2), "r"(A3), "r"(B.x), "r"(B.y))

__device__ __forceinline__ float fast_tanh(float x) {
    float y; asm("tanh.approx.f32 %0, %1;" : "=f"(y) : "f"(x)); return y;
}
__device__ __forceinline__ unsigned pack2(float a, float b) {
    __half2 h = __floats2half2_rn(a, b);
    return *reinterpret_cast<unsigned*>(&h);
}

// GEMM1: A + B(W1) from SMEM, both prefetched 2 kt ahead. bw[2][4] arrives
// preloaded with kt=0 (slot 0) and kt=1 (slot 1) from before the barrier.
__device__ __forceinline__ void gemm_w1(const unsigned* __restrict__ As,
                                        const uint2* __restrict__ w1s,
                                        uint2 bw[2][4],
                                        const float* __restrict__ b1s,
                                        int lane, int nt0, float acc[4][4])
{
    const int r0 = lane >> 2;
    const int c0 = lane & 3;
#pragma unroll
    for (int t = 0; t < 4; t++) {
        float2 bp = *reinterpret_cast<const float2*>(&b1s[(nt0 + t) * 8 + 2 * c0]);
        acc[t][0] = bp.x; acc[t][1] = bp.y;
        acc[t][2] = bp.x; acc[t][3] = bp.y;
    }

    unsigned aw[2][4];
#pragma unroll
    for (int q = 0; q < 2; q++) {
        const unsigned* Aq = As + q * 8;
        aw[q][0] = Aq[r0 * ASP + c0];
        aw[q][1] = Aq[(r0 + 8) * ASP + c0];
        aw[q][2] = Aq[r0 * ASP + c0 + 4];
        aw[q][3] = Aq[(r0 + 8) * ASP + c0 + 4];
    }

#pragma unroll
    for (int kt = 0; kt < NKT; kt++) {
        const int cur = kt & 1;
        unsigned a0 = aw[cur][0], a1 = aw[cur][1], a2 = aw[cur][2], a3 = aw[cur][3];
        uint2 b0 = bw[cur][0], b1v = bw[cur][1], b2v = bw[cur][2], b3 = bw[cur][3];
        if (kt + 2 < NKT) {
            const unsigned* An = As + (kt + 2) * 8;
            aw[cur][0] = An[r0 * ASP + c0];
            aw[cur][1] = An[(r0 + 8) * ASP + c0];
            aw[cur][2] = An[r0 * ASP + c0 + 4];
            aw[cur][3] = An[(r0 + 8) * ASP + c0 + 4];
#pragma unroll
            for (int t = 0; t < 4; t++)
                bw[cur][t] = w1s[((kt + 2) * NNT + nt0 + t) * 32 + lane];
        }
        MMA16(acc[0], a0, a1, a2, a3, b0);
        MMA16(acc[1], a0, a1, a2, a3, b1v);
        MMA16(acc[2], a0, a1, a2, a3, b2v);
        MMA16(acc[3], a0, a1, a2, a3, b3);
    }
}

// GEMM2: A from SMEM prefetched 2 kt ahead, B (W2) from persistent registers.
__device__ __forceinline__ void gemm_w2(const unsigned* __restrict__ As,
                                        const uint2 w2r[NKT][4],
                                        const float* __restrict__ b2s,
                                        int lane, int nt0, float acc[4][4])
{
    const int r0 = lane >> 2;
    const int c0 = lane & 3;
#pragma unroll
    for (int t = 0; t < 4; t++) {
        float2 bp = *reinterpret_cast<const float2*>(&b2s[(nt0 + t) * 8 + 2 * c0]);
        acc[t][0] = bp.x; acc[t][1] = bp.y;
        acc[t][2] = bp.x; acc[t][3] = bp.y;
    }

    unsigned aw[2][4];
#pragma unroll
    for (int q = 0; q < 2; q++) {
        const unsigned* Aq = As + q * 8;
        aw[q][0] = Aq[r0 * ASP + c0];
        aw[q][1] = Aq[(r0 + 8) * ASP + c0];
        aw[q][2] = Aq[r0 * ASP + c0 + 4];
        aw[q][3] = Aq[(r0 + 8) * ASP + c0 + 4];
    }

#pragma unroll
    for (int kt = 0; kt < NKT; kt++) {
        const int cur = kt & 1;
        unsigned a0 = aw[cur][0], a1 = aw[cur][1], a2 = aw[cur][2], a3 = aw[cur][3];
        if (kt + 2 < NKT) {
            const unsigned* An = As + (kt + 2) * 8;
            aw[cur][0] = An[r0 * ASP + c0];
            aw[cur][1] = An[(r0 + 8) * ASP + c0];
            aw[cur][2] = An[r0 * ASP + c0 + 4];
            aw[cur][3] = An[(r0 + 8) * ASP + c0 + 4];
        }
        MMA16(acc[0], a0, a1, a2, a3, w2r[kt][0]);
        MMA16(acc[1], a0, a1, a2, a3, w2r[kt][1]);
        MMA16(acc[2], a0, a1, a2, a3, w2r[kt][2]);
        MMA16(acc[3], a0, a1, a2, a3, w2r[kt][3]);
    }
}

__global__ void __launch_bounds__(256, 1)
node_kernel(const float* __restrict__ z0, const float* __restrict__ tg,
            const float* __restrict__ b1, const float* __restrict__ b2,
            float* __restrict__ out)
{
    extern __shared__ unsigned char smem_raw[];
    uint2*    w1s = reinterpret_cast<uint2*>(smem_raw + SMEM_W1);
    unsigned* Atf = reinterpret_cast<unsigned*>(smem_raw + SMEM_ATF);
    unsigned* Htf = reinterpret_cast<unsigned*>(smem_raw + SMEM_HTF);
    float*    b1s = reinterpret_cast<float*>(smem_raw + SMEM_B1);
    float*    b2s = reinterpret_cast<float*>(smem_raw + SMEM_B2);

    const int tid  = threadIdx.x;
    const int lane = tid & 31;
    const int wid  = tid >> 5;           // 0..7
    const int nt0  = wid * 4;            // 4 n-tiles per warp
    const int r0   = lane >> 2;
    const int c0   = lane & 3;
    const int row0 = blockIdx.x * MROW;

    // ---- W1 fragments -> SMEM (once); biases -> SMEM ----
    {
        const uint4* src = reinterpret_cast<const uint4*>(WfG);
        uint4* dst = reinterpret_cast<uint4*>(w1s);
#pragma unroll
        for (int i = 0; i < WREC / 2 / 256; i++)
            dst[i * 256 + tid] = src[i * 256 + tid];
    }
    if (tid < ZDIM) { b1s[tid] = b1[tid]; b2s[tid] = b2[tid]; }

    // ---- W2 fragments -> persistent registers (once, 128 regs) ----
    uint2 w2r[NKT][4];
    {
        const uint2* w2g = WfG + WREC;
#pragma unroll
        for (int kt = 0; kt < NKT; kt++)
#pragma unroll
            for (int t = 0; t < 4; t++)
                w2r[kt][t] = w2g[(kt * NNT + nt0 + t) * 32 + lane];
    }

    float zr[4][4], ar[4][4], acc[4][4];
    uint2 bw[2][4];

    // Preload W1 kt=0 (slot 0) and kt=1 (slot 1) — static data, safe pre-barrier.
#define PRELOAD_BW()                                                           \
    do {                                                                       \
        _Pragma("unroll")                                                      \
        for (int q = 0; q < 2; q++)                                            \
            _Pragma("unroll")                                                  \
            for (int t = 0; t < 4; t++)                                        \
                bw[q][t] = w1s[(q * NNT + nt0 + t) * 32 + lane];               \
    } while (0)

    // ---- initial state ----
#pragma unroll
    for (int t = 0; t < 4; t++) {
        int cb = (nt0 + t) * 8 + 2 * c0;
        float2 v0 = *reinterpret_cast<const float2*>(&z0[(row0 + r0) * ZDIM + cb]);
        float2 v1 = *reinterpret_cast<const float2*>(&z0[(row0 + r0 + 8) * ZDIM + cb]);
        zr[t][0] = v0.x; zr[t][1] = v0.y; zr[t][2] = v1.x; zr[t][3] = v1.y;
        int cu = (nt0 + t) * 4 + c0;
        Atf[r0 * ASP + cu]       = pack2(v0.x, v0.y);
        Atf[(r0 + 8) * ASP + cu] = pack2(v1.x, v1.y);
    }
    PRELOAD_BW();
    __syncthreads();

    // f(z): GEMM1 -> tanh -> Htf -> sync -> GEMM2
#define FEVAL()                                                                \
    do {                                                                       \
        gemm_w1(Atf, w1s, bw, b1s, lane, nt0, acc);                            \
        _Pragma("unroll")                                                      \
        for (int t = 0; t < 4; t++) {                                          \
            int cu = (nt0 + t) * 4 + c0;                                       \
            Htf[r0 * ASP + cu] =                                               \
                pack2(fast_tanh(acc[t][0]), fast_tanh(acc[t][1]));             \
            Htf[(r0 + 8) * ASP + cu] =                                         \
                pack2(fast_tanh(acc[t][2]), fast_tanh(acc[t][3]));             \
        }                                                                      \
        __syncthreads();                                                       \
        gemm_w2(Htf, w2r, b2s, lane, nt0, acc);                                \
    } while (0)

    for (int s = 0; s < TLEN - 1; s++) {
        const float hs = tg[s + 1] - tg[s];
        const float h6 = hs * (1.0f / 6.0f);
        const float h3 = hs * (1.0f / 3.0f);
        const float h2 = hs * 0.5f;

        // ---- k1 ----
        FEVAL();
#pragma unroll
        for (int t = 0; t < 4; t++) {
            int cu = (nt0 + t) * 4 + c0;
            Atf[r0 * ASP + cu] =
                pack2(fmaf(h2, acc[t][0], zr[t][0]), fmaf(h2, acc[t][1], zr[t][1]));
            Atf[(r0 + 8) * ASP + cu] =
                pack2(fmaf(h2, acc[t][2], zr[t][2]), fmaf(h2, acc[t][3], zr[t][3]));
#pragma unroll
            for (int d = 0; d < 4; d++)
                ar[t][d] = fmaf(h6, acc[t][d], zr[t][d]);
        }
        PRELOAD_BW();
        __syncthreads();

        // ---- k2 ----
        FEVAL();
#pragma unroll
        for (int t = 0; t < 4; t++) {
            int cu = (nt0 + t) * 4 + c0;
            Atf[r0 * ASP + cu] =
                pack2(fmaf(h2, acc[t][0], zr[t][0]), fmaf(h2, acc[t][1], zr[t][1]));
            Atf[(r0 + 8) * ASP + cu] =
                pack2(fmaf(h2, acc[t][2], zr[t][2]), fmaf(h2, acc[t][3], zr[t][3]));
#pragma unroll
            for (int d = 0; d < 4; d++)
                ar[t][d] = fmaf(h3, acc[t][d], ar[t][d]);
        }
        PRELOAD_BW();
        __syncthreads();

        // ---- k3 ----
        FEVAL();
#pragma unroll
        for (int t = 0; t < 4; t++) {
            int cu = (nt0 + t) * 4 + c0;
            Atf[r0 * ASP + cu] =
                pack2(fmaf(hs, acc[t][0], zr[t][0]), fmaf(hs, acc[t][1], zr[t][1]));
            Atf[(r0 + 8) * ASP + cu] =
                pack2(fmaf(hs, acc[t][2], zr[t][2]), fmaf(hs, acc[t][3], zr[t][3]));
#pragma unroll
            for (int d = 0; d < 4; d++)
                ar[t][d] = fmaf(h3, acc[t][d], ar[t][d]);
        }
        PRELOAD_BW();
        __syncthreads();

        // ---- k4 + state update ----
        FEVAL();
#pragma unroll
        for (int t = 0; t < 4; t++) {
#pragma unroll
            for (int d = 0; d < 4; d++)
                zr[t][d] = fmaf(h6, acc[t][d], ar[t][d]);
            int cu = (nt0 + t) * 4 + c0;
            Atf[r0 * ASP + cu]       = pack2(zr[t][0], zr[t][1]);
            Atf[(r0 + 8) * ASP + cu] = pack2(zr[t][2], zr[t][3]);
        }
        PRELOAD_BW();
        __syncthreads();
    }

#pragma unroll
    for (int t = 0; t < 4; t++) {
        int cb = (nt0 + t) * 8 + 2 * c0;
        float2 v0 = {zr[t][0], zr[t][1]};
        float2 v1 = {zr[t][2], zr[t][3]};
        *reinterpret_cast<float2*>(&out[(row0 + r0) * ZDIM + cb])     = v0;
        *reinterpret_cast<float2*>(&out[(row0 + r0 + 8) * ZDIM + cb]) = v1;
    }
}

extern "C" void kernel_launch(void* const* d_in, const int* in_sizes, int n_in,
                              void* d_out, int out_size)
{
    const float* z0 = (const float*)d_in[0];
    const float* t  = (const float*)d_in[1];
    const float* W1 = (const float*)d_in[2];
    const float* b1 = (const float*)d_in[3];
    const float* W2 = (const float*)d_in[4];
    const float* b2 = (const float*)d_in[5];
    float* out = (float*)d_out;

    cudaFuncSetAttribute(node_kernel,
                         cudaFuncAttributeMaxDynamicSharedMemorySize, SMEM_TOT);

    prep_kernel<<<(2 * WREC + 255) / 256, 256>>>(W1, W2);
    node_kernel<<<NCTA, 256, SMEM_TOT>>>(z0, t, b1, b2, out);
}